// round 15
// baseline (speedup 1.0000x reference)
#include <cuda_runtime.h>
#include <math.h>
#include <stdint.h>

#define NV 35709
#define NF 70789
#define NFP1 (NF + 1)
#define BATCH 32
#define M3 (3 * NV)   // 107127
#define NV3 (NV * 3)

// Output packing: face_color | landmark_p | fst
#define SZ_FC (BATCH * NV * 3)
#define OFF_FC 0
#define OFF_LM (SZ_FC)
#define SZ_LM (BATCH * 68 * 2)
#define OFF_FST (OFF_LM + SZ_LM)

// SH constants
#define C_Y0 0.8862269254527580f
#define C_Y1 1.7724538509055159f
#define C_Y4 2.4270324400f
#define C_Y6 0.7006239800f
#define C_Y8 1.2135162200f

#define FBLOCKS ((NFP1 + 15) / 16)
#define VBLOCKS ((NV + 7) / 8)
#define GEMM_BLOCKS ((M3 + 127) / 128)   // 837

#define ASTRIDE 132    // floats per kk-row in transposed A tile (16B-aligned rows)
#define CSTRIDE 36     // floats per k-row in coeff tile (tx*16B segments aligned)

// -------- scratch (device globals; batch-innermost layouts) --------
__device__ float4 g_fs[NV * BATCH];
__device__ float4 g_fnorm[NFP1 * BATCH];
__device__ float  g_tex[M3 * BATCH];
__device__ float  g_rot[BATCH * 9];
__device__ float  g_mean[3];               // f32 mean (bits load-bearing)
__device__ double g_mean_d[3];
__device__ double g_part[64 * 3];
__device__ unsigned long long g_spill[(size_t)GEMM_BLOCKS * 8 * 256];

// ---- f32x2 packed helpers ----
__device__ __forceinline__ unsigned long long pack2(float x, float y) {
    unsigned long long r;
    asm("mov.b64 %0, {%1, %2};" : "=l"(r) : "f"(x), "f"(y));
    return r;
}
__device__ __forceinline__ void unpack2(unsigned long long v, float& x, float& y) {
    asm("mov.b64 {%0, %1}, %2;" : "=f"(x), "=f"(y) : "l"(v));
}
__device__ __forceinline__ unsigned long long fma2(
    unsigned long long a, unsigned long long b, unsigned long long c) {
    unsigned long long d;
    asm("fma.rn.f32x2 %0, %1, %2, %3;" : "=l"(d) : "l"(a), "l"(b), "l"(c));
    return d;
}

// ---- cp.async helpers ----
__device__ __forceinline__ uint32_t su32(const void* p) {
    uint32_t a;
    asm("{ .reg .u64 t; cvta.to.shared.u64 t, %1; cvt.u32.u64 %0, t; }"
        : "=r"(a) : "l"(p));
    return a;
}
__device__ __forceinline__ void cp4(uint32_t dst, const float* src, int szbytes) {
    asm volatile("cp.async.ca.shared.global [%0], [%1], 4, %2;"
                 :: "r"(dst), "l"(src), "r"(szbytes));
}
__device__ __forceinline__ void cp_commit() {
    asm volatile("cp.async.commit_group;");
}
template <int N> __device__ __forceinline__ void cp_wait() {
    asm volatile("cp.async.wait_group %0;" :: "n"(N));
}

// ---------------------------------------------------------------------------
// Kernel A1/A2: parallel meanshape mean + rotations (UNCHANGED)
// ---------------------------------------------------------------------------
#define CHUNK 558
__global__ __launch_bounds__(256) void setup_partial_kernel(
    const float* __restrict__ meanshape) {
    __shared__ double sx[256], sy[256], sz[256];
    int t = threadIdx.x;
    int start = blockIdx.x * CHUNK;
    int end = start + CHUNK; if (end > NV) end = NV;
    double ax = 0.0, ay = 0.0, az = 0.0;
    for (int i = start + t; i < end; i += 256) {
        ax += (double)meanshape[3 * i + 0];
        ay += (double)meanshape[3 * i + 1];
        az += (double)meanshape[3 * i + 2];
    }
    sx[t] = ax; sy[t] = ay; sz[t] = az;
    __syncthreads();
    for (int s = 128; s > 0; s >>= 1) {
        if (t < s) { sx[t] += sx[t + s]; sy[t] += sy[t + s]; sz[t] += sz[t + s]; }
        __syncthreads();
    }
    if (t == 0) {
        g_part[blockIdx.x * 3 + 0] = sx[0];
        g_part[blockIdx.x * 3 + 1] = sy[0];
        g_part[blockIdx.x * 3 + 2] = sz[0];
    }
}

__global__ void setup_final_kernel(const float* __restrict__ coeff) {
    int t = threadIdx.x;
    if (t == 0) {
        double mx = 0.0, my = 0.0, mz = 0.0;
        for (int i = 0; i < 64; i++) {
            mx += g_part[i * 3 + 0];
            my += g_part[i * 3 + 1];
            mz += g_part[i * 3 + 2];
        }
        g_mean_d[0] = mx / (double)NV;
        g_mean_d[1] = my / (double)NV;
        g_mean_d[2] = mz / (double)NV;
        g_mean[0] = (float)(mx / (double)NV);
        g_mean[1] = (float)(my / (double)NV);
        g_mean[2] = (float)(mz / (double)NV);
    }
    if (t < BATCH) {
        const float* c = coeff + t * 277;
        float ax0 = c[244], ay0 = c[245], az0 = c[246];
        float cx = cosf(ax0), sxr = sinf(ax0);
        float cy = cosf(ay0), syr = sinf(ay0);
        float cz = cosf(az0), szr = sinf(az0);
        float Rx[9] = {1, 0, 0,   0, cx, -sxr,   0, sxr, cx};
        float Ry[9] = {cy, 0, syr,   0, 1, 0,   -syr, 0, cy};
        float Rz[9] = {cz, -szr, 0,   szr, cz, 0,   0, 0, 1};
        float Tm[9], R[9];
        #pragma unroll
        for (int i = 0; i < 3; i++)
            #pragma unroll
            for (int j = 0; j < 3; j++) {
                float s = 0.f;
                #pragma unroll
                for (int k = 0; k < 3; k++) s += Rz[i * 3 + k] * Ry[k * 3 + j];
                Tm[i * 3 + j] = s;
            }
        #pragma unroll
        for (int i = 0; i < 3; i++)
            #pragma unroll
            for (int j = 0; j < 3; j++) {
                float s = 0.f;
                #pragma unroll
                for (int k = 0; k < 3; k++) s += Tm[i * 3 + k] * Rx[k * 3 + j];
                R[i * 3 + j] = s;
            }
        #pragma unroll
        for (int i = 0; i < 3; i++)
            #pragma unroll
            for (int j = 0; j < 3; j++)
                g_rot[t * 9 + i * 3 + j] = R[j * 3 + i];
    }
}

// ---------------------------------------------------------------------------
// Kernel B1: fs GEMM — cp.async staging into TRANSPOSED A tile [kk][row]
// (stride 132) + vectorized LDS.128 for both operands:
//   A quad (rows ty*4..+3) = one LDS.128; B quad (batches tx*4..+3,
//   CSTRIDE=36 -> 16B aligned) = one LDS.128.  6 LDS -> 2 LDS per kk.
// Values and FMA chain order BIT-IDENTICAL (load-bearing).
// acc80 spill at id->ex boundary unchanged.
// ---------------------------------------------------------------------------
__global__ __launch_bounds__(256) void gemm_fs_kernel(
    const float* __restrict__ idBase, const float* __restrict__ exBase,
    const float* __restrict__ coeff, const float* __restrict__ meanshape) {
    __shared__ __align__(16) float Cs2[144 * CSTRIDE];   // 20.7 KB
    __shared__ __align__(16) float As[3][16 * ASTRIDE];  // 25.3 KB
    int t = threadIdx.x;
    int i0 = blockIdx.x * 128;

    for (int idx = t; idx < BATCH * 144; idx += 256) {
        int b = idx / 144, j = idx - b * 144;
        Cs2[j * CSTRIDE + b] = coeff[b * 277 + j];
    }

    int tx = t & 7;
    int ty = t >> 3;
    int sr = t >> 4;
    int sk = t & 15;
    uint32_t asb[3] = { su32(&As[0][0]), su32(&As[1][0]), su32(&As[2][0]) };

    unsigned long long acc[4][2];
    #pragma unroll
    for (int r = 0; r < 4; r++)
        #pragma unroll
        for (int p = 0; p < 2; p++) acc[r][p] = 0ULL;

    // stage chunk cn into transposed buffer dst: element (row, sk) -> [sk][row]
    #define STAGE_FS(cn, dst) do { \
        const float* Ap_; int ld_, kb_; \
        if ((cn) < 5) { Ap_ = idBase; ld_ = 80; kb_ = (cn) * 16; } \
        else          { Ap_ = exBase; ld_ = 64; kb_ = ((cn) - 5) * 16; } \
        _Pragma("unroll") \
        for (int j_ = 0; j_ < 8; j_++) { \
            int r_ = sr + j_ * 16; \
            int row_ = i0 + r_; \
            int ok_ = (row_ < M3); \
            const float* src_ = Ap_ + (size_t)(ok_ ? row_ : 0) * ld_ + kb_ + sk; \
            cp4((dst) + (uint32_t)((sk * ASTRIDE + r_) * 4), src_, ok_ ? 4 : 0); \
        } } while (0)

    STAGE_FS(0, asb[0]); cp_commit();
    STAGE_FS(1, asb[1]); cp_commit();

    #pragma unroll
    for (int ci = 0; ci < 9; ci++) {
        if (ci < 8) cp_wait<1>(); else cp_wait<0>();
        __syncthreads();
        if (ci <= 6) { STAGE_FS(ci + 2, asb[(ci + 2) % 3]); cp_commit(); }

        const float* buf = &As[ci % 3][0];
        int k0 = ci * 16;
        #pragma unroll
        for (int kk = 0; kk < 16; kk++) {
            int k = k0 + kk;
            float4 av = *reinterpret_cast<const float4*>(&buf[kk * ASTRIDE + ty * 4]);
            float4 bv = *reinterpret_cast<const float4*>(&Cs2[k * CSTRIDE + tx * 4]);
            unsigned long long b01 = pack2(bv.x, bv.y);
            unsigned long long b23 = pack2(bv.z, bv.w);
            unsigned long long pa0 = pack2(av.x, av.x), pa1 = pack2(av.y, av.y);
            unsigned long long pa2 = pack2(av.z, av.z), pa3 = pack2(av.w, av.w);
            acc[0][0] = fma2(pa0, b01, acc[0][0]); acc[0][1] = fma2(pa0, b23, acc[0][1]);
            acc[1][0] = fma2(pa1, b01, acc[1][0]); acc[1][1] = fma2(pa1, b23, acc[1][1]);
            acc[2][0] = fma2(pa2, b01, acc[2][0]); acc[2][1] = fma2(pa2, b23, acc[2][1]);
            acc[3][0] = fma2(pa3, b01, acc[3][0]); acc[3][1] = fma2(pa3, b23, acc[3][1]);
        }

        if (ci == 4) {
            unsigned long long* sp = g_spill + (size_t)blockIdx.x * 8 * 256;
            #pragma unroll
            for (int r = 0; r < 4; r++)
                #pragma unroll
                for (int p = 0; p < 2; p++) {
                    sp[(r * 2 + p) * 256 + t] = acc[r][p];
                    acc[r][p] = 0ULL;
                }
        }
    }
    #undef STAGE_FS

    const unsigned long long* sp = g_spill + (size_t)blockIdx.x * 8 * 256;
    float* fsf = (float*)g_fs;
    #pragma unroll
    for (int r = 0; r < 4; r++) {
        int row = i0 + ty * 4 + r;
        if (row >= M3) continue;
        int v = row / 3;
        int c = row - 3 * v;
        float ms = meanshape[row];
        float mn = g_mean[c];
        #pragma unroll
        for (int p = 0; p < 2; p++) {
            float lo80, hi80, lo64, hi64;
            unpack2(sp[(r * 2 + p) * 256 + t], lo80, hi80);
            unpack2(acc[r][p], lo64, hi64);
            int b = tx * 4 + 2 * p;
            float s0 = __fadd_rn(__fadd_rn(lo80, lo64), ms);
            fsf[((size_t)v * BATCH + b) * 4 + c] = __fsub_rn(s0, mn);
            float s1 = __fadd_rn(__fadd_rn(hi80, hi64), ms);
            fsf[((size_t)v * BATCH + b + 1) * 4 + c] = __fsub_rn(s1, mn);
        }
    }
}

// ---------------------------------------------------------------------------
// Kernel B2: tex GEMM — same transposed/vectorized scheme
// ---------------------------------------------------------------------------
__global__ __launch_bounds__(256) void gemm_tex_kernel(
    const float* __restrict__ texBase, const float* __restrict__ coeff,
    const float* __restrict__ meantex) {
    __shared__ __align__(16) float Cs2[112 * CSTRIDE];   // 16.1 KB
    __shared__ __align__(16) float As[3][16 * ASTRIDE];  // 25.3 KB
    int t = threadIdx.x;
    int i0 = blockIdx.x * 128;

    for (int idx = t; idx < BATCH * 112; idx += 256) {
        int b = idx / 112, j = idx - b * 112;
        Cs2[j * CSTRIDE + b] = (j < 100) ? coeff[b * 277 + 144 + j] : 0.f;
    }

    int tx = t & 7;
    int ty = t >> 3;
    int sr = t >> 4;
    int sk = t & 15;
    uint32_t asb[3] = { su32(&As[0][0]), su32(&As[1][0]), su32(&As[2][0]) };

    unsigned long long acc[4][2];
    #pragma unroll
    for (int r = 0; r < 4; r++)
        #pragma unroll
        for (int p = 0; p < 2; p++) acc[r][p] = 0ULL;

    #define STAGE_TX(cn, dst) do { \
        int kb_ = (cn) * 16; \
        _Pragma("unroll") \
        for (int j_ = 0; j_ < 8; j_++) { \
            int r_ = sr + j_ * 16; \
            int row_ = i0 + r_; \
            int k_ = kb_ + sk; \
            int ok_ = (row_ < M3 && k_ < 100); \
            const float* src_ = texBase + (size_t)(ok_ ? row_ : 0) * 100 + (ok_ ? k_ : 0); \
            cp4((dst) + (uint32_t)((sk * ASTRIDE + r_) * 4), src_, ok_ ? 4 : 0); \
        } } while (0)

    STAGE_TX(0, asb[0]); cp_commit();
    STAGE_TX(1, asb[1]); cp_commit();

    #pragma unroll
    for (int ci = 0; ci < 7; ci++) {
        if (ci < 6) cp_wait<1>(); else cp_wait<0>();
        __syncthreads();
        if (ci <= 4) { STAGE_TX(ci + 2, asb[(ci + 2) % 3]); cp_commit(); }

        const float* buf = &As[ci % 3][0];
        int k0 = ci * 16;
        #pragma unroll
        for (int kk = 0; kk < 16; kk++) {
            int k = k0 + kk;
            float4 av = *reinterpret_cast<const float4*>(&buf[kk * ASTRIDE + ty * 4]);
            float4 bv = *reinterpret_cast<const float4*>(&Cs2[k * CSTRIDE + tx * 4]);
            unsigned long long b01 = pack2(bv.x, bv.y);
            unsigned long long b23 = pack2(bv.z, bv.w);
            unsigned long long pa0 = pack2(av.x, av.x), pa1 = pack2(av.y, av.y);
            unsigned long long pa2 = pack2(av.z, av.z), pa3 = pack2(av.w, av.w);
            acc[0][0] = fma2(pa0, b01, acc[0][0]); acc[0][1] = fma2(pa0, b23, acc[0][1]);
            acc[1][0] = fma2(pa1, b01, acc[1][0]); acc[1][1] = fma2(pa1, b23, acc[1][1]);
            acc[2][0] = fma2(pa2, b01, acc[2][0]); acc[2][1] = fma2(pa2, b23, acc[2][1]);
            acc[3][0] = fma2(pa3, b01, acc[3][0]); acc[3][1] = fma2(pa3, b23, acc[3][1]);
        }
    }
    #undef STAGE_TX

    #pragma unroll
    for (int r = 0; r < 4; r++) {
        int row = i0 + ty * 4 + r;
        if (row >= M3) continue;
        float mt = meantex[row];
        #pragma unroll
        for (int p = 0; p < 2; p++) {
            float lo, hi;
            unpack2(acc[r][p], lo, hi);
            int b = tx * 4 + 2 * p;
            g_tex[(size_t)row * BATCH + b] = lo + mt;
            g_tex[(size_t)row * BATCH + b + 1] = hi + mt;
        }
    }
}

// ---------------------------------------------------------------------------
// Kernel C: MERGED face normals + fst (UNCHANGED)
// ---------------------------------------------------------------------------
__global__ __launch_bounds__(256) void facenorm_fst_kernel(
    const int* __restrict__ face_buf, const float* __restrict__ coeff,
    float* __restrict__ out) {
    __shared__ float sbuf[BATCH * 9 + BATCH * 3 + 8 * BATCH * 3];
    int t = threadIdx.x;

    if (blockIdx.x < FBLOCKS) {
        int w = t >> 5;
        int lane = t & 31;
        int fbase = (blockIdx.x * 8 + w) * 2;
        #pragma unroll
        for (int u = 0; u < 2; u++) {
            int f = fbase + u;
            if (f > NF) continue;
            float4* dst = g_fnorm + (size_t)f * BATCH + lane;
            if (f == NF) { *dst = make_float4(0.f, 0.f, 0.f, 0.f); continue; }
            int i1 = face_buf[f * 3 + 0];
            int i2 = face_buf[f * 3 + 1];
            int i3 = face_buf[f * 3 + 2];
            float4 p1 = g_fs[(size_t)i1 * BATCH + lane];
            float4 p2 = g_fs[(size_t)i2 * BATCH + lane];
            float4 p3 = g_fs[(size_t)i3 * BATCH + lane];
            float e1x = __fsub_rn(p1.x, p2.x), e1y = __fsub_rn(p1.y, p2.y), e1z = __fsub_rn(p1.z, p2.z);
            float e2x = __fsub_rn(p2.x, p3.x), e2y = __fsub_rn(p2.y, p3.y), e2z = __fsub_rn(p2.z, p3.z);
            float cx = __fmaf_rn(e1y, e2z, -__fmul_rn(e1z, e2y));
            float cy = __fmaf_rn(e1z, e2x, -__fmul_rn(e1x, e2z));
            float cz = __fmaf_rn(e1x, e2y, -__fmul_rn(e1y, e2x));
            float n2 = __fadd_rn(__fadd_rn(__fmul_rn(cx, cx), __fmul_rn(cy, cy)), __fmul_rn(cz, cz));
            float len = sqrtf(n2);
            float d = fmaxf(len, 1e-12f);
            *dst = make_float4(__fdiv_rn(cx, d), __fdiv_rn(cy, d), __fdiv_rn(cz, d), 0.f);
        }
    } else {
        float* srot = sbuf;
        float* strans = sbuf + BATCH * 9;
        float* sfst = sbuf + BATCH * 9 + BATCH * 3;
        for (int idx = t; idx < BATCH * 9; idx += 256) srot[idx] = g_rot[idx];
        for (int idx = t; idx < BATCH * 3; idx += 256)
            strans[idx] = coeff[(idx / 3) * 277 + 274 + (idx % 3)];
        __syncthreads();

        int blk = blockIdx.x - FBLOCKS;
        int w = t >> 5;
        int lane = t & 31;
        int v = blk * 8 + w;

        if (v < NV) {
            const float* rot = srot + lane * 9;
            const float* tr = strans + lane * 3;
            float4 fs4 = g_fs[(size_t)v * BATCH + lane];
            float* fo = sfst + (w * BATCH + lane) * 3;
            fo[0] = fs4.x * rot[0] + fs4.y * rot[3] + fs4.z * rot[6] + tr[0];
            fo[1] = fs4.x * rot[1] + fs4.y * rot[4] + fs4.z * rot[7] + tr[1];
            fo[2] = fs4.x * rot[2] + fs4.y * rot[5] + fs4.z * rot[8] + tr[2];
        }
        __syncthreads();

        size_t v0 = (size_t)blk * 8;
        int b = t >> 3;
        int wv = t & 7;
        if (v0 + wv < NV) {
            #pragma unroll
            for (int c = 0; c < 3; c++) {
                size_t go = (size_t)b * NV3 + (v0 + wv) * 3 + c;
                out[OFF_FST + go] = sfst[(wv * BATCH + b) * 3 + c];
            }
        }
    }
}

// ---------------------------------------------------------------------------
// Kernel D: vertex pass (UNCHANGED)
// ---------------------------------------------------------------------------
__global__ __launch_bounds__(256) void vertex_kernel(
    const int* __restrict__ point_buf, const float* __restrict__ coeff,
    float* __restrict__ out) {
    __shared__ float srot[BATCH * 9];
    __shared__ float sgsh[BATCH * 27];
    __shared__ float sfc[8 * BATCH * 3];

    int t = threadIdx.x;
    for (int idx = t; idx < BATCH * 9; idx += 256) srot[idx] = g_rot[idx];
    for (int idx = t; idx < BATCH * 27; idx += 256) {
        int b = idx / 27, j = idx - b * 27;
        sgsh[idx] = coeff[b * 277 + 247 + j] + (((j % 9) == 0) ? 0.8f : 0.f);
    }
    __syncthreads();

    int w = t >> 5;
    int lane = t & 31;
    int v = blockIdx.x * 8 + w;

    if (v < NV) {
        const int4* pb = (const int4*)point_buf;
        int4 q0 = pb[(size_t)v * 2 + 0];
        int4 q1 = pb[(size_t)v * 2 + 1];
        const float4* fn = g_fnorm;
        float nx = 0.f, ny = 0.f, nz = 0.f;
        float4 a;
        a = fn[(size_t)q0.x * BATCH + lane]; nx += a.x; ny += a.y; nz += a.z;
        a = fn[(size_t)q0.y * BATCH + lane]; nx += a.x; ny += a.y; nz += a.z;
        a = fn[(size_t)q0.z * BATCH + lane]; nx += a.x; ny += a.y; nz += a.z;
        a = fn[(size_t)q0.w * BATCH + lane]; nx += a.x; ny += a.y; nz += a.z;
        a = fn[(size_t)q1.x * BATCH + lane]; nx += a.x; ny += a.y; nz += a.z;
        a = fn[(size_t)q1.y * BATCH + lane]; nx += a.x; ny += a.y; nz += a.z;
        a = fn[(size_t)q1.z * BATCH + lane]; nx += a.x; ny += a.y; nz += a.z;
        a = fn[(size_t)q1.w * BATCH + lane]; nx += a.x; ny += a.y; nz += a.z;

        float len = sqrtf(nx * nx + ny * ny + nz * nz);
        float inv = 1.f / fmaxf(len, 1e-12f);
        nx *= inv; ny *= inv; nz *= inv;

        const float* rot = srot + lane * 9;
        float rx = nx * rot[0] + ny * rot[3] + nz * rot[6];
        float ry = nx * rot[1] + ny * rot[4] + nz * rot[7];
        float rz = nx * rot[2] + ny * rot[5] + nz * rot[8];

        float Y[9];
        Y[0] = C_Y0;
        Y[1] = -C_Y1 * ry;
        Y[2] = C_Y1 * rz;
        Y[3] = -C_Y1 * rx;
        Y[4] = C_Y4 * rx * ry;
        Y[5] = -C_Y4 * ry * rz;
        Y[6] = C_Y6 * (3.f * rz * rz - 1.f);
        Y[7] = -C_Y4 * rx * rz;
        Y[8] = C_Y8 * (rx * rx - ry * ry);

        const float* gsh = sgsh + lane * 27;
        float lit[3];
        #pragma unroll
        for (int c = 0; c < 3; c++) {
            float s = 0.f;
            #pragma unroll
            for (int k = 0; k < 9; k++) s += Y[k] * gsh[c * 9 + k];
            lit[c] = s;
        }

        const float* texv = g_tex + (size_t)v * 3 * BATCH;
        float* fc = sfc + (w * BATCH + lane) * 3;
        fc[0] = texv[0 * BATCH + lane] * lit[0];
        fc[1] = texv[1 * BATCH + lane] * lit[1];
        fc[2] = texv[2 * BATCH + lane] * lit[2];
    }
    __syncthreads();

    size_t v0 = (size_t)blockIdx.x * 8;
    int b = t >> 3;
    int wv = t & 7;
    if (v0 + wv < NV) {
        #pragma unroll
        for (int c = 0; c < 3; c++) {
            size_t go = (size_t)b * NV3 + (v0 + wv) * 3 + c;
            out[OFF_FC + go] = sfc[(wv * BATCH + b) * 3 + c];
        }
    }
}

// ---------------------------------------------------------------------------
// Kernel E: landmarks in fp64 (UNCHANGED)
// ---------------------------------------------------------------------------
__global__ __launch_bounds__(128) void landmark_kernel(
    const float* __restrict__ idBase, const float* __restrict__ exBase,
    const float* __restrict__ meanshape, const float* __restrict__ coeff,
    const int* __restrict__ keypoints, float* __restrict__ out) {
    int idx = blockIdx.x * 128 + threadIdx.x;
    if (idx >= BATCH * 68) return;
    int b = idx / 68, l = idx - b * 68;
    int v = keypoints[l];
    const float* c = coeff + b * 277;

    double fs[3];
    #pragma unroll
    for (int cc = 0; cc < 3; cc++) {
        int row = 3 * v + cc;
        const float* idr = idBase + (size_t)row * 80;
        const float* exr = exBase + (size_t)row * 64;
        double s = 0.0;
        for (int k = 0; k < 80; k++) s += (double)idr[k] * (double)c[k];
        for (int k = 0; k < 64; k++) s += (double)exr[k] * (double)c[80 + k];
        fs[cc] = s + (double)meanshape[row] - g_mean_d[cc];
    }

    double ax0 = (double)c[244], ay0 = (double)c[245], az0 = (double)c[246];
    double cx = cos(ax0), sx = sin(ax0);
    double cy = cos(ay0), sy = sin(ay0);
    double cz = cos(az0), sz = sin(az0);
    double R[3][3];
    R[0][0] = cz * cy;  R[0][1] = cz * sy * sx - sz * cx;  R[0][2] = cz * sy * cx + sz * sx;
    R[1][0] = sz * cy;  R[1][1] = sz * sy * sx + cz * cx;  R[1][2] = sz * sy * cx - cz * sx;
    R[2][0] = -sy;      R[2][1] = cy * sx;                 R[2][2] = cy * cx;
    double fst[3];
    #pragma unroll
    for (int j = 0; j < 3; j++)
        fst[j] = fs[0] * R[j][0] + fs[1] * R[j][1] + fs[2] * R[j][2]
               + (double)c[274 + j];

    double Zc = 10.0 - fst[2];
    double lx = (1015.0 * fst[0] + 112.0 * Zc) / Zc;
    double ly = (1015.0 * fst[1] + 112.0 * Zc) / Zc;
    out[OFF_LM + (size_t)idx * 2 + 0] = (float)lx;
    out[OFF_LM + (size_t)idx * 2 + 1] = (float)ly;
}

// ---------------------------------------------------------------------------
// Launcher (round-13 topology; gemm_fs in the profiled 4th slot)
// ---------------------------------------------------------------------------
extern "C" void kernel_launch(void* const* d_in, const int* in_sizes, int n_in,
                              void* d_out, int out_size) {
    const float* coeff     = (const float*)d_in[0];
    const float* idBase    = (const float*)d_in[1];
    const float* exBase    = (const float*)d_in[2];
    const float* texBase   = (const float*)d_in[3];
    const float* meanshape = (const float*)d_in[4];
    const float* meantex   = (const float*)d_in[5];
    const int*   face_buf  = (const int*)d_in[6];
    const int*   point_buf = (const int*)d_in[7];
    const int*   keypoints = (const int*)d_in[8];
    float* out = (float*)d_out;

    static cudaStream_t s2 = 0, s3 = 0;
    static cudaEvent_t evO = 0, evS = 0, evT = 0, evL = 0;
    if (!s2) {
        cudaStreamCreateWithFlags(&s2, cudaStreamNonBlocking);
        cudaStreamCreateWithFlags(&s3, cudaStreamNonBlocking);
        cudaEventCreateWithFlags(&evO, cudaEventDisableTiming);
        cudaEventCreateWithFlags(&evS, cudaEventDisableTiming);
        cudaEventCreateWithFlags(&evT, cudaEventDisableTiming);
        cudaEventCreateWithFlags(&evL, cudaEventDisableTiming);
    }

    cudaEventRecord(evO, 0);
    cudaStreamWaitEvent(s2, evO, 0);
    cudaStreamWaitEvent(s3, evO, 0);

    gemm_tex_kernel<<<GEMM_BLOCKS, 256, 0, s2>>>(texBase, coeff, meantex);
    cudaEventRecord(evT, s2);

    setup_partial_kernel<<<64, 256>>>(meanshape);
    setup_final_kernel<<<1, 256>>>(coeff);
    cudaEventRecord(evS, 0);

    gemm_fs_kernel<<<GEMM_BLOCKS, 256>>>(idBase, exBase, coeff, meanshape);

    facenorm_fst_kernel<<<FBLOCKS + VBLOCKS, 256>>>(face_buf, coeff, out);

    cudaStreamWaitEvent(s3, evS, 0);
    landmark_kernel<<<(BATCH * 68 + 127) / 128, 128, 0, s3>>>(
        idBase, exBase, meanshape, coeff, keypoints, out);
    cudaEventRecord(evL, s3);

    cudaStreamWaitEvent(0, evT, 0);
    vertex_kernel<<<(NV + 7) / 8, 256>>>(point_buf, coeff, out);
    cudaStreamWaitEvent(0, evL, 0);
}

// round 16
// speedup vs baseline: 1.0135x; 1.0135x over previous
#include <cuda_runtime.h>
#include <math.h>
#include <stdint.h>

#define NV 35709
#define NF 70789
#define NFP1 (NF + 1)
#define BATCH 32
#define M3 (3 * NV)   // 107127
#define NV3 (NV * 3)

#define SZ_FC (BATCH * NV * 3)
#define OFF_FC 0
#define OFF_LM (SZ_FC)
#define SZ_LM (BATCH * 68 * 2)
#define OFF_FST (OFF_LM + SZ_LM)

#define C_Y0 0.8862269254527580f
#define C_Y1 1.7724538509055159f
#define C_Y4 2.4270324400f
#define C_Y6 0.7006239800f
#define C_Y8 1.2135162200f

#define FBLOCKS ((NFP1 + 15) / 16)
#define VBLOCKS ((NV + 7) / 8)
#define GEMM_BLOCKS ((M3 + 127) / 128)   // 837

#define ASTRIDE 132
#define CSTRIDE 36
#define SSTRIDE 33     // epilogue staging stride (conflict-free lane reads)

// -------- scratch --------
__device__ float4 g_fs[NV * BATCH];
__device__ float4 g_fnorm[NFP1 * BATCH];
__device__ float  g_tex[M3 * BATCH];
__device__ float  g_rot[BATCH * 9];
__device__ float  g_mean[3];
__device__ double g_mean_d[3];
__device__ double g_part[64 * 3];
__device__ unsigned long long g_spill[(size_t)GEMM_BLOCKS * 8 * 256];

__device__ __forceinline__ unsigned long long pack2(float x, float y) {
    unsigned long long r;
    asm("mov.b64 %0, {%1, %2};" : "=l"(r) : "f"(x), "f"(y));
    return r;
}
__device__ __forceinline__ void unpack2(unsigned long long v, float& x, float& y) {
    asm("mov.b64 {%0, %1}, %2;" : "=f"(x), "=f"(y) : "l"(v));
}
__device__ __forceinline__ unsigned long long fma2(
    unsigned long long a, unsigned long long b, unsigned long long c) {
    unsigned long long d;
    asm("fma.rn.f32x2 %0, %1, %2, %3;" : "=l"(d) : "l"(a), "l"(b), "l"(c));
    return d;
}
__device__ __forceinline__ uint32_t su32(const void* p) {
    uint32_t a;
    asm("{ .reg .u64 t; cvta.to.shared.u64 t, %1; cvt.u32.u64 %0, t; }"
        : "=r"(a) : "l"(p));
    return a;
}
__device__ __forceinline__ void cp4(uint32_t dst, const float* src, int szbytes) {
    asm volatile("cp.async.ca.shared.global [%0], [%1], 4, %2;"
                 :: "r"(dst), "l"(src), "r"(szbytes));
}
__device__ __forceinline__ void cp_commit() {
    asm volatile("cp.async.commit_group;");
}
template <int N> __device__ __forceinline__ void cp_wait() {
    asm volatile("cp.async.wait_group %0;" :: "n"(N));
}

// ---------------------------------------------------------------------------
// Setup kernels (UNCHANGED)
// ---------------------------------------------------------------------------
#define CHUNK 558
__global__ __launch_bounds__(256) void setup_partial_kernel(
    const float* __restrict__ meanshape) {
    __shared__ double sx[256], sy[256], sz[256];
    int t = threadIdx.x;
    int start = blockIdx.x * CHUNK;
    int end = start + CHUNK; if (end > NV) end = NV;
    double ax = 0.0, ay = 0.0, az = 0.0;
    for (int i = start + t; i < end; i += 256) {
        ax += (double)meanshape[3 * i + 0];
        ay += (double)meanshape[3 * i + 1];
        az += (double)meanshape[3 * i + 2];
    }
    sx[t] = ax; sy[t] = ay; sz[t] = az;
    __syncthreads();
    for (int s = 128; s > 0; s >>= 1) {
        if (t < s) { sx[t] += sx[t + s]; sy[t] += sy[t + s]; sz[t] += sz[t + s]; }
        __syncthreads();
    }
    if (t == 0) {
        g_part[blockIdx.x * 3 + 0] = sx[0];
        g_part[blockIdx.x * 3 + 1] = sy[0];
        g_part[blockIdx.x * 3 + 2] = sz[0];
    }
}

__global__ void setup_final_kernel(const float* __restrict__ coeff) {
    int t = threadIdx.x;
    if (t == 0) {
        double mx = 0.0, my = 0.0, mz = 0.0;
        for (int i = 0; i < 64; i++) {
            mx += g_part[i * 3 + 0];
            my += g_part[i * 3 + 1];
            mz += g_part[i * 3 + 2];
        }
        g_mean_d[0] = mx / (double)NV;
        g_mean_d[1] = my / (double)NV;
        g_mean_d[2] = mz / (double)NV;
        g_mean[0] = (float)(mx / (double)NV);
        g_mean[1] = (float)(my / (double)NV);
        g_mean[2] = (float)(mz / (double)NV);
    }
    if (t < BATCH) {
        const float* c = coeff + t * 277;
        float ax0 = c[244], ay0 = c[245], az0 = c[246];
        float cx = cosf(ax0), sxr = sinf(ax0);
        float cy = cosf(ay0), syr = sinf(ay0);
        float cz = cosf(az0), szr = sinf(az0);
        float Rx[9] = {1, 0, 0,   0, cx, -sxr,   0, sxr, cx};
        float Ry[9] = {cy, 0, syr,   0, 1, 0,   -syr, 0, cy};
        float Rz[9] = {cz, -szr, 0,   szr, cz, 0,   0, 0, 1};
        float Tm[9], R[9];
        #pragma unroll
        for (int i = 0; i < 3; i++)
            #pragma unroll
            for (int j = 0; j < 3; j++) {
                float s = 0.f;
                #pragma unroll
                for (int k = 0; k < 3; k++) s += Rz[i * 3 + k] * Ry[k * 3 + j];
                Tm[i * 3 + j] = s;
            }
        #pragma unroll
        for (int i = 0; i < 3; i++)
            #pragma unroll
            for (int j = 0; j < 3; j++) {
                float s = 0.f;
                #pragma unroll
                for (int k = 0; k < 3; k++) s += Tm[i * 3 + k] * Rx[k * 3 + j];
                R[i * 3 + j] = s;
            }
        #pragma unroll
        for (int i = 0; i < 3; i++)
            #pragma unroll
            for (int j = 0; j < 3; j++)
                g_rot[t * 9 + i * 3 + j] = R[j * 3 + i];
    }
}

// ---------------------------------------------------------------------------
// Kernel B1: fs GEMM. Mainloop UNCHANGED (bit-exact). NEW epilogue: stage
// results in smem (reusing As) then warp-per-vertex float4 coalesced stores
// (512B/warp) instead of scattered 4B floats (4x sector traffic cut).
// ---------------------------------------------------------------------------
__global__ __launch_bounds__(256) void gemm_fs_kernel(
    const float* __restrict__ idBase, const float* __restrict__ exBase,
    const float* __restrict__ coeff, const float* __restrict__ meanshape) {
    __shared__ __align__(16) float Cs2[144 * CSTRIDE];
    __shared__ __align__(16) float As[3][16 * ASTRIDE];   // also epilogue stage
    int t = threadIdx.x;
    int i0 = blockIdx.x * 128;

    for (int idx = t; idx < BATCH * 144; idx += 256) {
        int b = idx / 144, j = idx - b * 144;
        Cs2[j * CSTRIDE + b] = coeff[b * 277 + j];
    }

    int tx = t & 7;
    int ty = t >> 3;
    int sr = t >> 4;
    int sk = t & 15;
    uint32_t asb[3] = { su32(&As[0][0]), su32(&As[1][0]), su32(&As[2][0]) };

    unsigned long long acc[4][2];
    #pragma unroll
    for (int r = 0; r < 4; r++)
        #pragma unroll
        for (int p = 0; p < 2; p++) acc[r][p] = 0ULL;

    #define STAGE_FS(cn, dst) do { \
        const float* Ap_; int ld_, kb_; \
        if ((cn) < 5) { Ap_ = idBase; ld_ = 80; kb_ = (cn) * 16; } \
        else          { Ap_ = exBase; ld_ = 64; kb_ = ((cn) - 5) * 16; } \
        _Pragma("unroll") \
        for (int j_ = 0; j_ < 8; j_++) { \
            int r_ = sr + j_ * 16; \
            int row_ = i0 + r_; \
            int ok_ = (row_ < M3); \
            const float* src_ = Ap_ + (size_t)(ok_ ? row_ : 0) * ld_ + kb_ + sk; \
            cp4((dst) + (uint32_t)((sk * ASTRIDE + r_) * 4), src_, ok_ ? 4 : 0); \
        } } while (0)

    STAGE_FS(0, asb[0]); cp_commit();
    STAGE_FS(1, asb[1]); cp_commit();

    #pragma unroll
    for (int ci = 0; ci < 9; ci++) {
        if (ci < 8) cp_wait<1>(); else cp_wait<0>();
        __syncthreads();
        if (ci <= 6) { STAGE_FS(ci + 2, asb[(ci + 2) % 3]); cp_commit(); }

        const float* buf = &As[ci % 3][0];
        int k0 = ci * 16;
        #pragma unroll
        for (int kk = 0; kk < 16; kk++) {
            int k = k0 + kk;
            float4 av = *reinterpret_cast<const float4*>(&buf[kk * ASTRIDE + ty * 4]);
            float4 bv = *reinterpret_cast<const float4*>(&Cs2[k * CSTRIDE + tx * 4]);
            unsigned long long b01 = pack2(bv.x, bv.y);
            unsigned long long b23 = pack2(bv.z, bv.w);
            unsigned long long pa0 = pack2(av.x, av.x), pa1 = pack2(av.y, av.y);
            unsigned long long pa2 = pack2(av.z, av.z), pa3 = pack2(av.w, av.w);
            acc[0][0] = fma2(pa0, b01, acc[0][0]); acc[0][1] = fma2(pa0, b23, acc[0][1]);
            acc[1][0] = fma2(pa1, b01, acc[1][0]); acc[1][1] = fma2(pa1, b23, acc[1][1]);
            acc[2][0] = fma2(pa2, b01, acc[2][0]); acc[2][1] = fma2(pa2, b23, acc[2][1]);
            acc[3][0] = fma2(pa3, b01, acc[3][0]); acc[3][1] = fma2(pa3, b23, acc[3][1]);
        }

        if (ci == 4) {
            unsigned long long* sp = g_spill + (size_t)blockIdx.x * 8 * 256;
            #pragma unroll
            for (int r = 0; r < 4; r++)
                #pragma unroll
                for (int p = 0; p < 2; p++) {
                    sp[(r * 2 + p) * 256 + t] = acc[r][p];
                    acc[r][p] = 0ULL;
                }
        }
    }
    #undef STAGE_FS

    // ---- NEW epilogue: stage into smem, then coalesced float4 stores ----
    const unsigned long long* sp = g_spill + (size_t)blockIdx.x * 8 * 256;
    __syncthreads();                     // As buffers dead; reuse as stage
    float* S = &As[0][0];                // [128][SSTRIDE]
    #pragma unroll
    for (int r = 0; r < 4; r++) {
        int rl = ty * 4 + r;
        int row = i0 + rl;
        float ms = (row < M3) ? meanshape[row] : 0.f;
        int c = row - 3 * (row / 3);
        float mn = g_mean[c];
        #pragma unroll
        for (int p = 0; p < 2; p++) {
            float lo80, hi80, lo64, hi64;
            unpack2(sp[(r * 2 + p) * 256 + t], lo80, hi80);
            unpack2(acc[r][p], lo64, hi64);
            int b = tx * 4 + 2 * p;
            float s0 = __fsub_rn(__fadd_rn(__fadd_rn(lo80, lo64), ms), mn);
            float s1 = __fsub_rn(__fadd_rn(__fadd_rn(hi80, hi64), ms), mn);
            S[rl * SSTRIDE + b] = s0;
            S[rl * SSTRIDE + b + 1] = s1;
        }
    }
    __syncthreads();

    // write phase: warp per vertex; lane = batch; float4(x,y,z,0) per store
    int w = t >> 5, lane = t & 31;
    int vfirst = i0 / 3;                         // first vertex touched
    int rowlast = i0 + 127; if (rowlast >= M3) rowlast = M3 - 1;
    int vlast = rowlast / 3;
    for (int v = vfirst + w; v <= vlast; v += 8) {
        int lr0 = 3 * v - i0;        // local row of component 0
        if (lr0 >= 0 && lr0 + 2 < 128) {
            float4 val;
            val.x = S[(lr0 + 0) * SSTRIDE + lane];
            val.y = S[(lr0 + 1) * SSTRIDE + lane];
            val.z = S[(lr0 + 2) * SSTRIDE + lane];
            val.w = 0.f;
            g_fs[(size_t)v * BATCH + lane] = val;
        } else {
            // boundary vertex: scalar writes for in-range components only
            float* fsf = (float*)g_fs;
            #pragma unroll
            for (int c = 0; c < 3; c++) {
                int lr = lr0 + c;
                if (lr >= 0 && lr < 128 && (i0 + lr) < M3)
                    fsf[((size_t)v * BATCH + lane) * 4 + c] = S[lr * SSTRIDE + lane];
            }
        }
    }
}

// ---------------------------------------------------------------------------
// Kernel B2: tex GEMM. Mainloop UNCHANGED. NEW coalesced epilogue.
// ---------------------------------------------------------------------------
__global__ __launch_bounds__(256) void gemm_tex_kernel(
    const float* __restrict__ texBase, const float* __restrict__ coeff,
    const float* __restrict__ meantex) {
    __shared__ __align__(16) float Cs2[112 * CSTRIDE];
    __shared__ __align__(16) float As[3][16 * ASTRIDE];
    int t = threadIdx.x;
    int i0 = blockIdx.x * 128;

    for (int idx = t; idx < BATCH * 112; idx += 256) {
        int b = idx / 112, j = idx - b * 112;
        Cs2[j * CSTRIDE + b] = (j < 100) ? coeff[b * 277 + 144 + j] : 0.f;
    }

    int tx = t & 7;
    int ty = t >> 3;
    int sr = t >> 4;
    int sk = t & 15;
    uint32_t asb[3] = { su32(&As[0][0]), su32(&As[1][0]), su32(&As[2][0]) };

    unsigned long long acc[4][2];
    #pragma unroll
    for (int r = 0; r < 4; r++)
        #pragma unroll
        for (int p = 0; p < 2; p++) acc[r][p] = 0ULL;

    #define STAGE_TX(cn, dst) do { \
        int kb_ = (cn) * 16; \
        _Pragma("unroll") \
        for (int j_ = 0; j_ < 8; j_++) { \
            int r_ = sr + j_ * 16; \
            int row_ = i0 + r_; \
            int k_ = kb_ + sk; \
            int ok_ = (row_ < M3 && k_ < 100); \
            const float* src_ = texBase + (size_t)(ok_ ? row_ : 0) * 100 + (ok_ ? k_ : 0); \
            cp4((dst) + (uint32_t)((sk * ASTRIDE + r_) * 4), src_, ok_ ? 4 : 0); \
        } } while (0)

    STAGE_TX(0, asb[0]); cp_commit();
    STAGE_TX(1, asb[1]); cp_commit();

    #pragma unroll
    for (int ci = 0; ci < 7; ci++) {
        if (ci < 6) cp_wait<1>(); else cp_wait<0>();
        __syncthreads();
        if (ci <= 4) { STAGE_TX(ci + 2, asb[(ci + 2) % 3]); cp_commit(); }

        const float* buf = &As[ci % 3][0];
        int k0 = ci * 16;
        #pragma unroll
        for (int kk = 0; kk < 16; kk++) {
            int k = k0 + kk;
            float4 av = *reinterpret_cast<const float4*>(&buf[kk * ASTRIDE + ty * 4]);
            float4 bv = *reinterpret_cast<const float4*>(&Cs2[k * CSTRIDE + tx * 4]);
            unsigned long long b01 = pack2(bv.x, bv.y);
            unsigned long long b23 = pack2(bv.z, bv.w);
            unsigned long long pa0 = pack2(av.x, av.x), pa1 = pack2(av.y, av.y);
            unsigned long long pa2 = pack2(av.z, av.z), pa3 = pack2(av.w, av.w);
            acc[0][0] = fma2(pa0, b01, acc[0][0]); acc[0][1] = fma2(pa0, b23, acc[0][1]);
            acc[1][0] = fma2(pa1, b01, acc[1][0]); acc[1][1] = fma2(pa1, b23, acc[1][1]);
            acc[2][0] = fma2(pa2, b01, acc[2][0]); acc[2][1] = fma2(pa2, b23, acc[2][1]);
            acc[3][0] = fma2(pa3, b01, acc[3][0]); acc[3][1] = fma2(pa3, b23, acc[3][1]);
        }
    }
    #undef STAGE_TX

    // ---- NEW epilogue: stage + fully coalesced 128B stores ----
    __syncthreads();
    float* S = &As[0][0];
    #pragma unroll
    for (int r = 0; r < 4; r++) {
        int rl = ty * 4 + r;
        int row = i0 + rl;
        float mt = (row < M3) ? meantex[row] : 0.f;
        #pragma unroll
        for (int p = 0; p < 2; p++) {
            float lo, hi;
            unpack2(acc[r][p], lo, hi);
            int b = tx * 4 + 2 * p;
            S[rl * SSTRIDE + b] = lo + mt;
            S[rl * SSTRIDE + b + 1] = hi + mt;
        }
    }
    __syncthreads();
    #pragma unroll
    for (int i = 0; i < 16; i++) {
        int idx = t + 256 * i;          // 0..4095
        int rl = idx >> 5, b = idx & 31;
        int row = i0 + rl;
        if (row < M3) g_tex[(size_t)row * BATCH + b] = S[rl * SSTRIDE + b];
    }
}

// ---------------------------------------------------------------------------
// Kernel C: MERGED face normals + fst (UNCHANGED)
// ---------------------------------------------------------------------------
__global__ __launch_bounds__(256) void facenorm_fst_kernel(
    const int* __restrict__ face_buf, const float* __restrict__ coeff,
    float* __restrict__ out) {
    __shared__ float sbuf[BATCH * 9 + BATCH * 3 + 8 * BATCH * 3];
    int t = threadIdx.x;

    if (blockIdx.x < FBLOCKS) {
        int w = t >> 5;
        int lane = t & 31;
        int fbase = (blockIdx.x * 8 + w) * 2;
        #pragma unroll
        for (int u = 0; u < 2; u++) {
            int f = fbase + u;
            if (f > NF) continue;
            float4* dst = g_fnorm + (size_t)f * BATCH + lane;
            if (f == NF) { *dst = make_float4(0.f, 0.f, 0.f, 0.f); continue; }
            int i1 = face_buf[f * 3 + 0];
            int i2 = face_buf[f * 3 + 1];
            int i3 = face_buf[f * 3 + 2];
            float4 p1 = g_fs[(size_t)i1 * BATCH + lane];
            float4 p2 = g_fs[(size_t)i2 * BATCH + lane];
            float4 p3 = g_fs[(size_t)i3 * BATCH + lane];
            float e1x = __fsub_rn(p1.x, p2.x), e1y = __fsub_rn(p1.y, p2.y), e1z = __fsub_rn(p1.z, p2.z);
            float e2x = __fsub_rn(p2.x, p3.x), e2y = __fsub_rn(p2.y, p3.y), e2z = __fsub_rn(p2.z, p3.z);
            float cx = __fmaf_rn(e1y, e2z, -__fmul_rn(e1z, e2y));
            float cy = __fmaf_rn(e1z, e2x, -__fmul_rn(e1x, e2z));
            float cz = __fmaf_rn(e1x, e2y, -__fmul_rn(e1y, e2x));
            float n2 = __fadd_rn(__fadd_rn(__fmul_rn(cx, cx), __fmul_rn(cy, cy)), __fmul_rn(cz, cz));
            float len = sqrtf(n2);
            float d = fmaxf(len, 1e-12f);
            *dst = make_float4(__fdiv_rn(cx, d), __fdiv_rn(cy, d), __fdiv_rn(cz, d), 0.f);
        }
    } else {
        float* srot = sbuf;
        float* strans = sbuf + BATCH * 9;
        float* sfst = sbuf + BATCH * 9 + BATCH * 3;
        for (int idx = t; idx < BATCH * 9; idx += 256) srot[idx] = g_rot[idx];
        for (int idx = t; idx < BATCH * 3; idx += 256)
            strans[idx] = coeff[(idx / 3) * 277 + 274 + (idx % 3)];
        __syncthreads();

        int blk = blockIdx.x - FBLOCKS;
        int w = t >> 5;
        int lane = t & 31;
        int v = blk * 8 + w;

        if (v < NV) {
            const float* rot = srot + lane * 9;
            const float* tr = strans + lane * 3;
            float4 fs4 = g_fs[(size_t)v * BATCH + lane];
            float* fo = sfst + (w * BATCH + lane) * 3;
            fo[0] = fs4.x * rot[0] + fs4.y * rot[3] + fs4.z * rot[6] + tr[0];
            fo[1] = fs4.x * rot[1] + fs4.y * rot[4] + fs4.z * rot[7] + tr[1];
            fo[2] = fs4.x * rot[2] + fs4.y * rot[5] + fs4.z * rot[8] + tr[2];
        }
        __syncthreads();

        size_t v0 = (size_t)blk * 8;
        int b = t >> 3;
        int wv = t & 7;
        if (v0 + wv < NV) {
            #pragma unroll
            for (int c = 0; c < 3; c++) {
                size_t go = (size_t)b * NV3 + (v0 + wv) * 3 + c;
                out[OFF_FST + go] = sfst[(wv * BATCH + b) * 3 + c];
            }
        }
    }
}

// ---------------------------------------------------------------------------
// Kernel D: vertex pass (UNCHANGED)
// ---------------------------------------------------------------------------
__global__ __launch_bounds__(256) void vertex_kernel(
    const int* __restrict__ point_buf, const float* __restrict__ coeff,
    float* __restrict__ out) {
    __shared__ float srot[BATCH * 9];
    __shared__ float sgsh[BATCH * 27];
    __shared__ float sfc[8 * BATCH * 3];

    int t = threadIdx.x;
    for (int idx = t; idx < BATCH * 9; idx += 256) srot[idx] = g_rot[idx];
    for (int idx = t; idx < BATCH * 27; idx += 256) {
        int b = idx / 27, j = idx - b * 27;
        sgsh[idx] = coeff[b * 277 + 247 + j] + (((j % 9) == 0) ? 0.8f : 0.f);
    }
    __syncthreads();

    int w = t >> 5;
    int lane = t & 31;
    int v = blockIdx.x * 8 + w;

    if (v < NV) {
        const int4* pb = (const int4*)point_buf;
        int4 q0 = pb[(size_t)v * 2 + 0];
        int4 q1 = pb[(size_t)v * 2 + 1];
        const float4* fn = g_fnorm;
        float nx = 0.f, ny = 0.f, nz = 0.f;
        float4 a;
        a = fn[(size_t)q0.x * BATCH + lane]; nx += a.x; ny += a.y; nz += a.z;
        a = fn[(size_t)q0.y * BATCH + lane]; nx += a.x; ny += a.y; nz += a.z;
        a = fn[(size_t)q0.z * BATCH + lane]; nx += a.x; ny += a.y; nz += a.z;
        a = fn[(size_t)q0.w * BATCH + lane]; nx += a.x; ny += a.y; nz += a.z;
        a = fn[(size_t)q1.x * BATCH + lane]; nx += a.x; ny += a.y; nz += a.z;
        a = fn[(size_t)q1.y * BATCH + lane]; nx += a.x; ny += a.y; nz += a.z;
        a = fn[(size_t)q1.z * BATCH + lane]; nx += a.x; ny += a.y; nz += a.z;
        a = fn[(size_t)q1.w * BATCH + lane]; nx += a.x; ny += a.y; nz += a.z;

        float len = sqrtf(nx * nx + ny * ny + nz * nz);
        float inv = 1.f / fmaxf(len, 1e-12f);
        nx *= inv; ny *= inv; nz *= inv;

        const float* rot = srot + lane * 9;
        float rx = nx * rot[0] + ny * rot[3] + nz * rot[6];
        float ry = nx * rot[1] + ny * rot[4] + nz * rot[7];
        float rz = nx * rot[2] + ny * rot[5] + nz * rot[8];

        float Y[9];
        Y[0] = C_Y0;
        Y[1] = -C_Y1 * ry;
        Y[2] = C_Y1 * rz;
        Y[3] = -C_Y1 * rx;
        Y[4] = C_Y4 * rx * ry;
        Y[5] = -C_Y4 * ry * rz;
        Y[6] = C_Y6 * (3.f * rz * rz - 1.f);
        Y[7] = -C_Y4 * rx * rz;
        Y[8] = C_Y8 * (rx * rx - ry * ry);

        const float* gsh = sgsh + lane * 27;
        float lit[3];
        #pragma unroll
        for (int c = 0; c < 3; c++) {
            float s = 0.f;
            #pragma unroll
            for (int k = 0; k < 9; k++) s += Y[k] * gsh[c * 9 + k];
            lit[c] = s;
        }

        const float* texv = g_tex + (size_t)v * 3 * BATCH;
        float* fc = sfc + (w * BATCH + lane) * 3;
        fc[0] = texv[0 * BATCH + lane] * lit[0];
        fc[1] = texv[1 * BATCH + lane] * lit[1];
        fc[2] = texv[2 * BATCH + lane] * lit[2];
    }
    __syncthreads();

    size_t v0 = (size_t)blockIdx.x * 8;
    int b = t >> 3;
    int wv = t & 7;
    if (v0 + wv < NV) {
        #pragma unroll
        for (int c = 0; c < 3; c++) {
            size_t go = (size_t)b * NV3 + (v0 + wv) * 3 + c;
            out[OFF_FC + go] = sfc[(wv * BATCH + b) * 3 + c];
        }
    }
}

// ---------------------------------------------------------------------------
// Kernel E: landmarks in fp64 (UNCHANGED)
// ---------------------------------------------------------------------------
__global__ __launch_bounds__(128) void landmark_kernel(
    const float* __restrict__ idBase, const float* __restrict__ exBase,
    const float* __restrict__ meanshape, const float* __restrict__ coeff,
    const int* __restrict__ keypoints, float* __restrict__ out) {
    int idx = blockIdx.x * 128 + threadIdx.x;
    if (idx >= BATCH * 68) return;
    int b = idx / 68, l = idx - b * 68;
    int v = keypoints[l];
    const float* c = coeff + b * 277;

    double fs[3];
    #pragma unroll
    for (int cc = 0; cc < 3; cc++) {
        int row = 3 * v + cc;
        const float* idr = idBase + (size_t)row * 80;
        const float* exr = exBase + (size_t)row * 64;
        double s = 0.0;
        for (int k = 0; k < 80; k++) s += (double)idr[k] * (double)c[k];
        for (int k = 0; k < 64; k++) s += (double)exr[k] * (double)c[80 + k];
        fs[cc] = s + (double)meanshape[row] - g_mean_d[cc];
    }

    double ax0 = (double)c[244], ay0 = (double)c[245], az0 = (double)c[246];
    double cx = cos(ax0), sx = sin(ax0);
    double cy = cos(ay0), sy = sin(ay0);
    double cz = cos(az0), sz = sin(az0);
    double R[3][3];
    R[0][0] = cz * cy;  R[0][1] = cz * sy * sx - sz * cx;  R[0][2] = cz * sy * cx + sz * sx;
    R[1][0] = sz * cy;  R[1][1] = sz * sy * sx + cz * cx;  R[1][2] = sz * sy * cx - cz * sx;
    R[2][0] = -sy;      R[2][1] = cy * sx;                 R[2][2] = cy * cx;
    double fst[3];
    #pragma unroll
    for (int j = 0; j < 3; j++)
        fst[j] = fs[0] * R[j][0] + fs[1] * R[j][1] + fs[2] * R[j][2]
               + (double)c[274 + j];

    double Zc = 10.0 - fst[2];
    double lx = (1015.0 * fst[0] + 112.0 * Zc) / Zc;
    double ly = (1015.0 * fst[1] + 112.0 * Zc) / Zc;
    out[OFF_LM + (size_t)idx * 2 + 0] = (float)lx;
    out[OFF_LM + (size_t)idx * 2 + 1] = (float)ly;
}

// ---------------------------------------------------------------------------
// Launcher (UNCHANGED topology; gemm_fs in profiled 4th slot)
// ---------------------------------------------------------------------------
extern "C" void kernel_launch(void* const* d_in, const int* in_sizes, int n_in,
                              void* d_out, int out_size) {
    const float* coeff     = (const float*)d_in[0];
    const float* idBase    = (const float*)d_in[1];
    const float* exBase    = (const float*)d_in[2];
    const float* texBase   = (const float*)d_in[3];
    const float* meanshape = (const float*)d_in[4];
    const float* meantex   = (const float*)d_in[5];
    const int*   face_buf  = (const int*)d_in[6];
    const int*   point_buf = (const int*)d_in[7];
    const int*   keypoints = (const int*)d_in[8];
    float* out = (float*)d_out;

    static cudaStream_t s2 = 0, s3 = 0;
    static cudaEvent_t evO = 0, evS = 0, evT = 0, evL = 0;
    if (!s2) {
        cudaStreamCreateWithFlags(&s2, cudaStreamNonBlocking);
        cudaStreamCreateWithFlags(&s3, cudaStreamNonBlocking);
        cudaEventCreateWithFlags(&evO, cudaEventDisableTiming);
        cudaEventCreateWithFlags(&evS, cudaEventDisableTiming);
        cudaEventCreateWithFlags(&evT, cudaEventDisableTiming);
        cudaEventCreateWithFlags(&evL, cudaEventDisableTiming);
    }

    cudaEventRecord(evO, 0);
    cudaStreamWaitEvent(s2, evO, 0);
    cudaStreamWaitEvent(s3, evO, 0);

    gemm_tex_kernel<<<GEMM_BLOCKS, 256, 0, s2>>>(texBase, coeff, meantex);
    cudaEventRecord(evT, s2);

    setup_partial_kernel<<<64, 256>>>(meanshape);
    setup_final_kernel<<<1, 256>>>(coeff);
    cudaEventRecord(evS, 0);

    gemm_fs_kernel<<<GEMM_BLOCKS, 256>>>(idBase, exBase, coeff, meanshape);

    facenorm_fst_kernel<<<FBLOCKS + VBLOCKS, 256>>>(face_buf, coeff, out);

    cudaStreamWaitEvent(s3, evS, 0);
    landmark_kernel<<<(BATCH * 68 + 127) / 128, 128, 0, s3>>>(
        idBase, exBase, meanshape, coeff, keypoints, out);
    cudaEventRecord(evL, s3);

    cudaStreamWaitEvent(0, evT, 0);
    vertex_kernel<<<(NV + 7) / 8, 256>>>(point_buf, coeff, out);
    cudaStreamWaitEvent(0, evL, 0);
}